// round 14
// baseline (speedup 1.0000x reference)
#include <cuda_runtime.h>

// PrevEmbedding fused, 4-warps-per-row (128 lanes x 3 float2):
//   out[row,:] = LN(gathered_row)*g+b + LN(pos_emb[t]+type_emb[ty])*eg+eb
// - LN only the 2048 gathered rows, never the 32000x768 table
// - 128 threads per row -> 8192 warps total -> ~55 warps/SM (~86% occ)
// - row-quad stat combine via named barrier (bar.sync quad,128): no CTA-wide sync
// - id candidates (int32/int64 views) loaded in parallel with dtype probes
// - params via L1 (hit after first warp), streaming output stores

#define HD     768
#define TPB    256          // 8 warps = 2 row-quads per CTA
#define RPC    2            // rows per CTA
#define LN_EPS 1e-5f

__device__ __forceinline__ void stcs2(float2* p, float2 v) {
    asm volatile("st.global.cs.v2.f32 [%0], {%1,%2};"
                 :: "l"(p), "f"(v.x), "f"(v.y) : "memory");
}

__global__ __launch_bounds__(TPB)
void prev_embedding_kernel(
    const float* __restrict__ cv,        // [V, H]
    const float* __restrict__ ocr,       // [B, N, H]
    const int*   __restrict__ raw,       // [B*T] int32 view (maybe int64 data)
    const float* __restrict__ cv_g,
    const float* __restrict__ cv_b,
    const float* __restrict__ ocr_g,
    const float* __restrict__ ocr_b,
    const float* __restrict__ pos_emb,   // [T, H]
    const float* __restrict__ type_emb,  // [2, H]
    const float* __restrict__ emb_g,
    const float* __restrict__ emb_b,
    float* __restrict__ out,             // [B*T, H]
    int V, int N, int T, int BT)
{
    __shared__ float4 s_red[RPC][4];     // [quad][warpInQuad] = {sx,sxx,sp,spp}

    const int tid   = threadIdx.x;
    const int wid   = tid >> 5;
    const int lane  = tid & 31;
    const int quad  = wid >> 2;          // 0..1
    const int wiq   = wid & 3;           // warp-in-quad
    const int h0    = wiq * 32 + lane;   // 0..127: lane position within row
    const int row   = blockIdx.x * RPC + quad;
    if (row >= BT) return;

    // --- id fetch: both dtype candidates + probes issued in parallel ---
    const int pr   = raw[1] | raw[3] | raw[5] | raw[7];  // uniform, L1 broadcast
    const int id32 = raw[row];
    const int id64 = raw[2 * row];
    const int id   = (pr == 0) ? id64 : id32;   // int64 view has zero odd words

    const int b = row / T;
    const int t = row - b * T;

    const int type_id = (t >= V) ? 1 : 0;       // faithful to reference (0 here)
    const float2* pe2 = (const float2*)(pos_emb + t * HD);
    const float2* te2 = (const float2*)(type_emb + type_id * HD);

    // pos/type loads are id-independent: in flight during id selection.
    float2 p[3];
    #pragma unroll
    for (int j = 0; j < 3; j++) {
        float2 a = pe2[h0 + 128 * j];
        float2 c = te2[h0 + 128 * j];
        p[j] = make_float2(a.x + c.x, a.y + c.y);
    }

    const float* src;
    const bool use_ocr = (id >= V);
    if (use_ocr) {
        int oi = id - V;
        if (oi > N - 1) oi = N - 1;
        src = ocr + ((long long)b * N + oi) * HD;
    } else {
        int ci = id < 0 ? 0 : (id > V - 1 ? V - 1 : id);
        src = cv + (long long)ci * HD;
    }
    const float2* s2 = (const float2*)src;

    float2 x[3];
    #pragma unroll
    for (int j = 0; j < 3; j++) x[j] = s2[h0 + 128 * j];

    float sx = 0.f, sxx = 0.f, sp = 0.f, spp = 0.f;
    #pragma unroll
    for (int j = 0; j < 3; j++) {
        sp  += p[j].x + p[j].y;
        spp += p[j].x * p[j].x + p[j].y * p[j].y;
        sx  += x[j].x + x[j].y;
        sxx += x[j].x * x[j].x + x[j].y * x[j].y;
    }

    #pragma unroll
    for (int off = 16; off > 0; off >>= 1) {
        sx  += __shfl_xor_sync(0xFFFFFFFFu, sx,  off);
        sxx += __shfl_xor_sync(0xFFFFFFFFu, sxx, off);
        sp  += __shfl_xor_sync(0xFFFFFFFFu, sp,  off);
        spp += __shfl_xor_sync(0xFFFFFFFFu, spp, off);
    }

    // cross-warp combine within the quad: independent named barrier per quad
    if (lane == 0) s_red[quad][wiq] = make_float4(sx, sxx, sp, spp);
    asm volatile("bar.sync %0, 128;" :: "r"(quad) : "memory");
    const float4 r0 = s_red[quad][0];
    const float4 r1 = s_red[quad][1];
    const float4 r2 = s_red[quad][2];
    const float4 r3 = s_red[quad][3];

    const float inv_h = 1.0f / (float)HD;
    const float mu_x = (r0.x + r1.x + r2.x + r3.x) * inv_h;
    const float rx   = rsqrtf(fmaxf((r0.y + r1.y + r2.y + r3.y) * inv_h - mu_x * mu_x, 0.f) + LN_EPS);
    const float mu_p = (r0.z + r1.z + r2.z + r3.z) * inv_h;
    const float rp   = rsqrtf(fmaxf((r0.w + r1.w + r2.w + r3.w) * inv_h - mu_p * mu_p, 0.f) + LN_EPS);

    const float2* gm  = (const float2*)(use_ocr ? ocr_g : cv_g);
    const float2* bm  = (const float2*)(use_ocr ? ocr_b : cv_b);
    const float2* egm = (const float2*)emb_g;
    const float2* ebm = (const float2*)emb_b;
    float2* o = (float2*)(out + (long long)row * HD);

    #pragma unroll
    for (int j = 0; j < 3; j++) {
        const int h = h0 + 128 * j;
        const float2 g  = gm[h];
        const float2 bb = bm[h];
        const float2 eg = egm[h];
        const float2 eb = ebm[h];
        float2 r;
        r.x = (x[j].x - mu_x) * rx * g.x + bb.x + (p[j].x - mu_p) * rp * eg.x + eb.x;
        r.y = (x[j].y - mu_x) * rx * g.y + bb.y + (p[j].y - mu_p) * rp * eg.y + eb.y;
        stcs2(o + h, r);
    }
}

extern "C" void kernel_launch(void* const* d_in, const int* in_sizes, int n_in,
                              void* d_out, int out_size) {
    const float* cv       = (const float*)d_in[0];   // [V, H]
    const float* ocr      = (const float*)d_in[1];   // [B, N, H]
    const int*   ids_raw  = (const int*)d_in[2];     // [B, T] int32 or int64
    const float* cv_g     = (const float*)d_in[3];
    const float* cv_b     = (const float*)d_in[4];
    const float* ocr_g    = (const float*)d_in[5];
    const float* ocr_b    = (const float*)d_in[6];
    const float* pos_emb  = (const float*)d_in[7];   // [T, H]
    const float* type_emb = (const float*)d_in[8];   // [2, H]
    const float* emb_g    = (const float*)d_in[9];
    const float* emb_b    = (const float*)d_in[10];
    float* out = (float*)d_out;

    const int Hs = in_sizes[3];             // 768
    const int V  = in_sizes[0] / Hs;        // 32000
    const int T  = in_sizes[7] / Hs;        // 128
    const int BT = in_sizes[2];             // 2048
    const int B  = BT / T;                  // 16
    const int N  = in_sizes[1] / (B * Hs);  // 50

    const int grid = (BT + RPC - 1) / RPC;  // 1024
    prev_embedding_kernel<<<grid, TPB>>>(cv, ocr, ids_raw,
                                         cv_g, cv_b, ocr_g, ocr_b,
                                         pos_emb, type_emb, emb_g, emb_b,
                                         out, V, N, T, BT);
}